// round 4
// baseline (speedup 1.0000x reference)
#include <cuda_runtime.h>
#include <cstdint>
#include <cstddef>

// ============================================================================
// Problem constants
// ============================================================================
static constexpr int BB  = 16;
static constexpr int SQ  = 2048;
static constexpr int DD  = 128;
static constexpr float QK_SCALE = 0.08838834764831845f;  // 1/sqrt(128)

// SMEM layout (bytes): Q/K/V tiles are 128x128 tf32 (stored as 4B bit patterns),
// mask tile is 128 rows x 144B (padded).
static constexpr int OFF_Q = 0;
static constexpr int OFF_K = 65536;
static constexpr int OFF_V = 131072;
static constexpr int OFF_M = 196608;
static constexpr int SMEM_TOTAL = OFF_M + 128 * 144;   // 215040 B

// ============================================================================
// Device globals (no dynamic allocation allowed)
// ============================================================================
__device__ int   g_mask_is_int32;
__device__ float g_inv[BB * SQ];

// ============================================================================
// Helpers
// ============================================================================
__device__ __forceinline__ uint32_t f2tf32(float f) {
    uint32_t r;
    asm("cvt.rna.tf32.f32 %0, %1;" : "=r"(r) : "f"(f));
    return r;
}

__device__ __forceinline__ void mma_tf32(float& c0, float& c1, float& c2, float& c3,
                                         uint32_t a0, uint32_t a1, uint32_t a2, uint32_t a3,
                                         uint32_t b0, uint32_t b1) {
    asm volatile(
        "mma.sync.aligned.m16n8k8.row.col.f32.tf32.tf32.f32 "
        "{%0,%1,%2,%3}, {%4,%5,%6,%7}, {%8,%9}, {%0,%1,%2,%3};"
        : "+f"(c0), "+f"(c1), "+f"(c2), "+f"(c3)
        : "r"(a0), "r"(a1), "r"(a2), "r"(a3), "r"(b0), "r"(b1));
}

// ============================================================================
// Kernel 0: detect mask serialization (bool/uint8 vs int32).
// ============================================================================
__global__ void detect_mask_kernel(const uint8_t* __restrict__ m) {
    int t = threadIdx.x;
    int bad = 0;
    for (int i = t; i < 4096; i += 32)
        if ((i & 3) && m[i]) bad = 1;
    unsigned any = __ballot_sync(0xffffffffu, bad);
    if (t == 0) g_mask_is_int32 = (any == 0) ? 1 : 0;
}

// ============================================================================
// Kernel A: flash attention tile. grid = (SQ/128, BB), 256 threads (8 warps).
// Each warp owns 16 query rows. Writes UNNORMALIZED exp(scores) to attn,
// out = (E@V)/rowsum, and 1/rowsum -> g_inv.
// ============================================================================
__global__ void __launch_bounds__(256, 1)
attn_kernel(const float* __restrict__ Qg, const float* __restrict__ Kg,
            const float* __restrict__ Vg, const void* __restrict__ maskg,
            float* __restrict__ outg, float* __restrict__ attng, int has_attn) {
    extern __shared__ char smem[];
    uint32_t* const Qs = (uint32_t*)(smem + OFF_Q);
    uint32_t* const Ks = (uint32_t*)(smem + OFF_K);
    uint32_t* const Vs = (uint32_t*)(smem + OFF_V);
    uint8_t*  const Ms = (uint8_t*)(smem + OFF_M);

    const int tid = threadIdx.x, wid = tid >> 5, lane = tid & 31;
    const int g = lane >> 2, t = lane & 3;          // mma groupID / threadID
    const int qt = blockIdx.x, b = blockIdx.y;
    const int m32 = g_mask_is_int32;

    // ---- stage Q once (fp32 -> tf32, swizzle c ^ ((r&7)<<2)) ----
    {
        const float* qsrc = Qg + ((size_t)(b * SQ + qt * 128)) * DD;
        #pragma unroll
        for (int i = 0; i < 16; i++) {
            int idx = tid + i * 256;
            int r = idx >> 5, f = idx & 31, c = f * 4;
            float4 v = ((const float4*)(qsrc + (size_t)r * DD))[f];
            uint4 w;
            w.x = f2tf32(v.x); w.y = f2tf32(v.y); w.z = f2tf32(v.z); w.w = f2tf32(v.w);
            *(uint4*)(Qs + r * 128 + (c ^ ((r & 7) << 2))) = w;
        }
    }

    // persistent accumulators: O tile (16 rows x 128 cols per warp) + rowsums
    float o[16][4];
    #pragma unroll
    for (int nt = 0; nt < 16; nt++) { o[nt][0] = o[nt][1] = o[nt][2] = o[nt][3] = 0.0f; }
    float lsum0 = 0.0f, lsum1 = 0.0f;

    const int qrow_l = wid * 16 + g;                     // CTA-local query row (and +8)
    const size_t qrow_g = (size_t)(b * SQ + qt * 128) + qrow_l;   // global query row

    for (int kt = 0; kt < 16; kt++) {
        // ---- stage K tile ----
        {
            const float* ksrc = Kg + ((size_t)(b * SQ + kt * 128)) * DD;
            #pragma unroll
            for (int i = 0; i < 16; i++) {
                int idx = tid + i * 256;
                int r = idx >> 5, f = idx & 31, c = f * 4;
                float4 v = ((const float4*)(ksrc + (size_t)r * DD))[f];
                uint4 w;
                w.x = f2tf32(v.x); w.y = f2tf32(v.y); w.z = f2tf32(v.z); w.w = f2tf32(v.w);
                *(uint4*)(Ks + r * 128 + (c ^ ((r & 7) << 2))) = w;
            }
        }
        // ---- stage V tile (swizzle c ^ ((r&3)<<3)) ----
        {
            const float* vsrc = Vg + ((size_t)(b * SQ + kt * 128)) * DD;
            #pragma unroll
            for (int i = 0; i < 16; i++) {
                int idx = tid + i * 256;
                int r = idx >> 5, f = idx & 31, c = f * 4;
                float4 v = ((const float4*)(vsrc + (size_t)r * DD))[f];
                uint4 w;
                w.x = f2tf32(v.x); w.y = f2tf32(v.y); w.z = f2tf32(v.z); w.w = f2tf32(v.w);
                *(uint4*)(Vs + r * 128 + (c ^ ((r & 3) << 3))) = w;
            }
        }
        // ---- stage mask tile (-> bytes, rows padded to 144B) ----
        if (m32) {
            const int* msrc = (const int*)maskg;
            #pragma unroll
            for (int i = 0; i < 16; i++) {
                int idx = tid + i * 256;                 // 4096 groups of 4 ints
                int r = idx >> 5, gi = idx & 31;
                size_t off = ((size_t)(b * SQ + qt * 128 + r)) * SQ + kt * 128 + 4 * gi;
                uint4 x = *(const uint4*)(msrc + off);
                uint32_t packed = (x.x & 0xffu) | ((x.y & 0xffu) << 8) |
                                  ((x.z & 0xffu) << 16) | ((x.w & 0xffu) << 24);
                *(uint32_t*)(Ms + r * 144 + 4 * gi) = packed;
            }
        } else {
            const uint8_t* msrc = (const uint8_t*)maskg;
            #pragma unroll
            for (int i = 0; i < 4; i++) {
                int idx = tid + i * 256;                 // 1024 groups of 16 bytes
                int r = idx >> 3, gq = idx & 7;
                size_t off = ((size_t)(b * SQ + qt * 128 + r)) * SQ + kt * 128 + 16 * gq;
                uint4 x = *(const uint4*)(msrc + off);
                *(uint4*)(Ms + r * 144 + 16 * gq) = x;
            }
        }
        __syncthreads();

        // ---- QK^T: scores C (16x128 per warp) ----
        float c[16][4];
        #pragma unroll
        for (int nt = 0; nt < 16; nt++) { c[nt][0] = c[nt][1] = c[nt][2] = c[nt][3] = 0.0f; }

        for (int ks = 0; ks < 16; ks++) {
            const int col0 = (8 * ks + t) ^ (g << 2);
            const int col4 = (8 * ks + 4 + t) ^ (g << 2);
            const uint32_t a0 = Qs[qrow_l * 128 + col0];
            const uint32_t a1 = Qs[(qrow_l + 8) * 128 + col0];
            const uint32_t a2 = Qs[qrow_l * 128 + col4];
            const uint32_t a3 = Qs[(qrow_l + 8) * 128 + col4];
            #pragma unroll
            for (int nt = 0; nt < 16; nt++) {
                const int kr = 8 * nt + g;
                const uint32_t b0 = Ks[kr * 128 + col0];
                const uint32_t b1 = Ks[kr * 128 + col4];
                mma_tf32(c[nt][0], c[nt][1], c[nt][2], c[nt][3], a0, a1, a2, a3, b0, b1);
            }
        }

        // ---- softmax numerator: mask, exp, rowsum, attn write (in-place in c) ----
        float* arow0 = attng + qrow_g * SQ + kt * 128;
        float* arow1 = arow0 + 8 * (size_t)SQ;
        const uint8_t* mrow0 = Ms + qrow_l * 144;
        const uint8_t* mrow1 = Ms + (qrow_l + 8) * 144;
        #pragma unroll
        for (int nt = 0; nt < 16; nt++) {
            const int cb = 8 * nt + 2 * t;
            uint32_t m0 = *(const uint16_t*)(mrow0 + cb);
            uint32_t m1 = *(const uint16_t*)(mrow1 + cb);
            float e0 = (m0 & 0xffu)  ? 0.0f : __expf(c[nt][0] * QK_SCALE);
            float e1 = (m0 >> 8)     ? 0.0f : __expf(c[nt][1] * QK_SCALE);
            float e2 = (m1 & 0xffu)  ? 0.0f : __expf(c[nt][2] * QK_SCALE);
            float e3 = (m1 >> 8)     ? 0.0f : __expf(c[nt][3] * QK_SCALE);
            c[nt][0] = e0; c[nt][1] = e1; c[nt][2] = e2; c[nt][3] = e3;
            lsum0 += e0 + e1;
            lsum1 += e2 + e3;
            if (has_attn) {
                *(float2*)(arow0 + cb) = make_float2(e0, e1);
                *(float2*)(arow1 + cb) = make_float2(e2, e3);
            }
        }

        // ---- PV: O += E @ V. Convert C-frag(ks) -> A-frag via shuffles. ----
        const int srcA = (lane & 0x1C) | ((lane & 3) >> 1);
        const int srcB = srcA + 2;
        const bool sel = lane & 1;
        #pragma unroll
        for (int ks = 0; ks < 16; ks++) {
            float v00 = __shfl_sync(0xffffffffu, c[ks][0], srcA);
            float v01 = __shfl_sync(0xffffffffu, c[ks][1], srcA);
            float v20 = __shfl_sync(0xffffffffu, c[ks][2], srcA);
            float v21 = __shfl_sync(0xffffffffu, c[ks][3], srcA);
            float w00 = __shfl_sync(0xffffffffu, c[ks][0], srcB);
            float w01 = __shfl_sync(0xffffffffu, c[ks][1], srcB);
            float w20 = __shfl_sync(0xffffffffu, c[ks][2], srcB);
            float w21 = __shfl_sync(0xffffffffu, c[ks][3], srcB);
            const uint32_t a0 = f2tf32(sel ? v01 : v00);
            const uint32_t a1 = f2tf32(sel ? v21 : v20);
            const uint32_t a2 = f2tf32(sel ? w01 : w00);
            const uint32_t a3 = f2tf32(sel ? w21 : w20);
            const int vr0 = 8 * ks + t;       // V rows for b0 / b1
            const int vr4 = vr0 + 4;
            #pragma unroll
            for (int nt = 0; nt < 16; nt++) {
                const int cc = (8 * nt + g) ^ (t << 3);
                const uint32_t b0 = Vs[vr0 * 128 + cc];
                const uint32_t b1 = Vs[vr4 * 128 + cc];
                mma_tf32(o[nt][0], o[nt][1], o[nt][2], o[nt][3], a0, a1, a2, a3, b0, b1);
            }
        }
        __syncthreads();
    }

    // ---- reduce rowsums across the quad (lanes sharing a row) ----
    lsum0 += __shfl_xor_sync(0xffffffffu, lsum0, 1);
    lsum0 += __shfl_xor_sync(0xffffffffu, lsum0, 2);
    lsum1 += __shfl_xor_sync(0xffffffffu, lsum1, 1);
    lsum1 += __shfl_xor_sync(0xffffffffu, lsum1, 2);
    const float inv0 = 1.0f / lsum0;
    const float inv1 = 1.0f / lsum1;
    if (t == 0) {
        g_inv[qrow_g]     = inv0;
        g_inv[qrow_g + 8] = inv1;
    }

    // ---- epilogue: out = O / rowsum ----
    float* orow0 = outg + qrow_g * DD;
    float* orow1 = orow0 + 8 * (size_t)DD;
    #pragma unroll
    for (int nt = 0; nt < 16; nt++) {
        const int cb = 8 * nt + 2 * t;
        *(float2*)(orow0 + cb) = make_float2(o[nt][0] * inv0, o[nt][1] * inv0);
        *(float2*)(orow1 + cb) = make_float2(o[nt][2] * inv1, o[nt][3] * inv1);
    }
}

// ============================================================================
// Kernel B: attn[i] *= 1/rowsum  (float4 grid-stride)
// ============================================================================
__global__ void __launch_bounds__(256)
norm_kernel(float* __restrict__ attn) {
    const size_t n4 = (size_t)BB * SQ * SQ / 4;       // 16,777,216 float4
    const size_t stride = (size_t)gridDim.x * 256;
    for (size_t i = (size_t)blockIdx.x * 256 + threadIdx.x; i < n4; i += stride) {
        float inv = g_inv[i >> 9];                     // 512 float4 per row
        float4 v = ((const float4*)attn)[i];
        v.x *= inv; v.y *= inv; v.z *= inv; v.w *= inv;
        ((float4*)attn)[i] = v;
    }
}

// ============================================================================
// Launch
// ============================================================================
extern "C" void kernel_launch(void* const* d_in, const int* in_sizes, int n_in,
                              void* d_out, int out_size) {
    const float* Q = (const float*)d_in[0];
    const float* K = (const float*)d_in[1];
    const float* V = (const float*)d_in[2];
    const void*  M = d_in[3];

    float* out = (float*)d_out;
    const long long out_elems  = (long long)BB * SQ * DD;              // 4,194,304
    const long long attn_elems = (long long)BB * SQ * SQ;              // 67,108,864
    int has_attn = ((long long)out_size >= out_elems + attn_elems) ? 1 : 0;
    float* attn = has_attn ? (out + out_elems) : out;   // dummy ptr if unused

    cudaFuncSetAttribute(attn_kernel,
                         cudaFuncAttributeMaxDynamicSharedMemorySize, SMEM_TOTAL);

    detect_mask_kernel<<<1, 32>>>((const uint8_t*)M);
    attn_kernel<<<dim3(SQ / 128, BB), 256, SMEM_TOTAL>>>(Q, K, V, M, out, attn, has_attn);
    if (has_attn)
        norm_kernel<<<8192, 256>>>(attn);
}

// round 6
// speedup vs baseline: 1.0834x; 1.0834x over previous
#include <cuda_runtime.h>
#include <cstdint>
#include <cstddef>

// ============================================================================
// Problem constants
// ============================================================================
static constexpr int BB  = 16;
static constexpr int SQ  = 2048;
static constexpr int DD  = 128;
static constexpr float QK_SCALE = 0.08838834764831845f;  // 1/sqrt(128)

// SMEM layout (bytes).
// Q: 128x128 tf32 (64 KB), staged once.
// K,V: double-buffered 64x128 tf32 tiles (32 KB each buffer).
// M: double-buffered mask tiles, 128 rows x 64 cols bytes, 80B pitch (10 KB each).
static constexpr int OFF_Q  = 0;
static constexpr int OFF_K  = 65536;     // + p*32768
static constexpr int OFF_V  = 131072;    // + p*32768
static constexpr int OFF_M  = 196608;    // + p*10240
static constexpr int M_PITCH = 80;
static constexpr int SMEM_TOTAL = OFF_M + 2 * 10240;   // 217088 B

// ============================================================================
// Device globals (no dynamic allocation allowed)
// ============================================================================
__device__ float g_inv[BB * SQ];

// ============================================================================
// Helpers
// ============================================================================
__device__ __forceinline__ uint32_t smem_u32(const void* p) {
    uint32_t a;
    asm("{ .reg .u64 t; cvta.to.shared.u64 t, %1; cvt.u32.u64 %0, t; }"
        : "=r"(a) : "l"(p));
    return a;
}

__device__ __forceinline__ uint32_t f2tf32(float f) {
    uint32_t r;
    asm("cvt.rna.tf32.f32 %0, %1;" : "=r"(r) : "f"(f));
    return r;
}

__device__ __forceinline__ void cp16(uint32_t dst, const void* src) {
    asm volatile("cp.async.cg.shared.global [%0], [%1], 16;"
                 :: "r"(dst), "l"(src) : "memory");
}
#define CP_COMMIT() asm volatile("cp.async.commit_group;" ::: "memory")
#define CP_WAIT0()  asm volatile("cp.async.wait_group 0;" ::: "memory")

__device__ __forceinline__ void mma_tf32(float& c0, float& c1, float& c2, float& c3,
                                         uint32_t a0, uint32_t a1, uint32_t a2, uint32_t a3,
                                         uint32_t b0, uint32_t b1) {
    asm volatile(
        "mma.sync.aligned.m16n8k8.row.col.f32.tf32.tf32.f32 "
        "{%0,%1,%2,%3}, {%4,%5,%6,%7}, {%8,%9}, {%0,%1,%2,%3};"
        : "+f"(c0), "+f"(c1), "+f"(c2), "+f"(c3)
        : "r"(a0), "r"(a1), "r"(a2), "r"(a3), "r"(b0), "r"(b1));
}

// ============================================================================
// Kernel A: flash attention tile. grid = (SQ/128, BB), 256 threads (8 warps).
// Each warp owns 16 query rows; 32 k-tiles of 64. K/V/mask staging is
// cp.async double-buffered and fully overlapped with compute.
// Writes UNNORMALIZED exp(scores) to attn, out = (E@V)/rowsum, 1/rowsum->g_inv.
// ============================================================================
__global__ void __launch_bounds__(256, 1)
attn_kernel(const float* __restrict__ Qg, const float* __restrict__ Kg,
            const float* __restrict__ Vg, const void* __restrict__ maskg,
            float* __restrict__ outg, float* __restrict__ attng, int has_attn) {
    extern __shared__ char smem[];
    const uint32_t sb = smem_u32(smem);
    uint32_t* const Qs = (uint32_t*)(smem + OFF_Q);

    const int tid = threadIdx.x, wid = tid >> 5, lane = tid & 31;
    const int g = lane >> 2, t = lane & 3;          // mma groupID / threadID
    const int qt = blockIdx.x, b = blockIdx.y;

    // ---- inline mask dtype detection (bool/uint8 vs int32) ----
    // int32 0/1 little-endian => bytes at offset%4!=0 are all zero.
    int bad = 0;
    {
        uint32_t w = ((const uint32_t*)maskg)[tid & 63];   // first 256 B
        if (w & 0xffffff00u) bad = 1;
    }
    const int m32 = __syncthreads_or(bad) ? 0 : 1;

    const uint8_t* const mbase =
        (const uint8_t*)maskg;   // byte path base (int32 path casts separately)
    const size_t mask_row0 = (size_t)(b * SQ + qt * 128);

    // ---- issue cp.async prefetch of tile kt into parity p ----
    auto issue_prefetch = [&](int kt, int p) {
        const char* ksrc = (const char*)(Kg + ((size_t)(b * SQ + kt * 64)) * DD);
        const char* vsrc = (const char*)(Vg + ((size_t)(b * SQ + kt * 64)) * DD);
        const uint32_t kb = sb + OFF_K + p * 32768;
        const uint32_t vb = sb + OFF_V + p * 32768;
        #pragma unroll
        for (int j = 0; j < 8; j++) {
            int ci = tid + j * 256;            // 2048 16B-chunks per tile
            int r = ci >> 5, f = ci & 31;      // 64 rows x 32 chunks
            cp16(kb + (r * 128 + ((f * 4) ^ ((r & 7) << 2))) * 4,
                 ksrc + r * 512 + f * 16);
            cp16(vb + (r * 128 + ((f * 4) ^ ((r & 3) << 3))) * 4,
                 vsrc + r * 512 + f * 16);
        }
        if (!m32) {
            const uint8_t* msrc = mbase + mask_row0 * SQ + kt * 64;
            const uint32_t mb = sb + OFF_M + p * 10240;
            #pragma unroll
            for (int j = 0; j < 2; j++) {
                int ci = tid + j * 256;        // 512 16B-chunks (128 rows x 4)
                int r = ci >> 2, gq = ci & 3;
                cp16(mb + r * M_PITCH + gq * 16, msrc + (size_t)r * SQ + gq * 16);
            }
        }
        CP_COMMIT();
    };

    issue_prefetch(0, 0);

    // ---- stage Q once (fp32 -> tf32, swizzle c ^ ((r&7)<<2)) ----
    {
        const float* qsrc = Qg + ((size_t)(b * SQ + qt * 128)) * DD;
        #pragma unroll
        for (int i = 0; i < 16; i++) {
            int idx = tid + i * 256;
            int r = idx >> 5, f = idx & 31, c = f * 4;
            float4 v = ((const float4*)(qsrc + (size_t)r * DD))[f];
            uint4 w;
            w.x = f2tf32(v.x); w.y = f2tf32(v.y); w.z = f2tf32(v.z); w.w = f2tf32(v.w);
            *(uint4*)(Qs + r * 128 + (c ^ ((r & 7) << 2))) = w;
        }
    }

    // persistent accumulators: O tile (16 rows x 128 cols per warp) + rowsums
    float o[16][4];
    #pragma unroll
    for (int nt = 0; nt < 16; nt++) { o[nt][0] = o[nt][1] = o[nt][2] = o[nt][3] = 0.0f; }
    float lsum0 = 0.0f, lsum1 = 0.0f;

    const int qrow_l = wid * 16 + g;                     // CTA-local query row (and +8)
    const size_t qrow_g = (size_t)(b * SQ + qt * 128) + qrow_l;

    const int srcA = (lane & 0x1C) | ((lane & 3) >> 1);  // C->A frag shuffle sources
    const int srcB = srcA + 2;
    const bool sel = lane & 1;

    for (int kt = 0; kt < 32; kt++) {
        const int p = kt & 1;
        uint32_t* const Ks = (uint32_t*)(smem + OFF_K + p * 32768);
        uint32_t* const Vs = (uint32_t*)(smem + OFF_V + p * 32768);
        uint8_t*  const Ms = (uint8_t*)(smem + OFF_M + p * 10240);

        CP_WAIT0();
        __syncthreads();   // tile kt landed; all warps done with buffer p^1's prior use

        // ---- in-place fp32 -> tf32 conversion of K and V (conflict-free) ----
        #pragma unroll
        for (int j = 0; j < 8; j++) {
            int ci = tid + j * 256;
            uint4* pk = (uint4*)(Ks + ci * 4);
            uint4 x = *pk;
            x.x = f2tf32(__uint_as_float(x.x)); x.y = f2tf32(__uint_as_float(x.y));
            x.z = f2tf32(__uint_as_float(x.z)); x.w = f2tf32(__uint_as_float(x.w));
            *pk = x;
            uint4* pv = (uint4*)(Vs + ci * 4);
            uint4 y = *pv;
            y.x = f2tf32(__uint_as_float(y.x)); y.y = f2tf32(__uint_as_float(y.y));
            y.z = f2tf32(__uint_as_float(y.z)); y.w = f2tf32(__uint_as_float(y.w));
            *pv = y;
        }
        // ---- int32 mask fallback: direct stage (packed to bytes) ----
        if (m32) {
            const int* msrc = (const int*)maskg;
            #pragma unroll
            for (int i = 0; i < 8; i++) {
                int idx = tid + i * 256;               // 2048 groups of 4 ints
                int r = idx >> 4, gi = idx & 15;
                size_t off = (mask_row0 + r) * SQ + kt * 64 + 4 * gi;
                uint4 x = *(const uint4*)(msrc + off);
                uint32_t packed = (x.x & 0xffu) | ((x.y & 0xffu) << 8) |
                                  ((x.z & 0xffu) << 16) | ((x.w & 0xffu) << 24);
                *(uint32_t*)(Ms + r * M_PITCH + 4 * gi) = packed;
            }
        }
        // ---- prefetch next tile into the other buffers (overlaps compute) ----
        if (kt < 31) issue_prefetch(kt + 1, p ^ 1);
        __syncthreads();

        // ---- QK^T: scores C (16x64 per warp) ----
        float c[8][4];
        #pragma unroll
        for (int nt = 0; nt < 8; nt++) { c[nt][0] = c[nt][1] = c[nt][2] = c[nt][3] = 0.0f; }

        #pragma unroll
        for (int ks = 0; ks < 16; ks++) {
            const int col0 = (8 * ks + t) ^ (g << 2);
            const int col4 = (8 * ks + 4 + t) ^ (g << 2);
            const uint32_t a0 = Qs[qrow_l * 128 + col0];
            const uint32_t a1 = Qs[(qrow_l + 8) * 128 + col0];
            const uint32_t a2 = Qs[qrow_l * 128 + col4];
            const uint32_t a3 = Qs[(qrow_l + 8) * 128 + col4];
            #pragma unroll
            for (int nt = 0; nt < 8; nt++) {
                const int kr = 8 * nt + g;
                const uint32_t b0 = Ks[kr * 128 + col0];
                const uint32_t b1 = Ks[kr * 128 + col4];
                mma_tf32(c[nt][0], c[nt][1], c[nt][2], c[nt][3], a0, a1, a2, a3, b0, b1);
            }
        }

        // ---- softmax numerator: mask, exp, rowsum, attn write ----
        float* arow0 = attng + qrow_g * SQ + kt * 64;
        float* arow1 = arow0 + 8 * (size_t)SQ;
        const uint8_t* mrow0 = Ms + qrow_l * M_PITCH;
        const uint8_t* mrow1 = Ms + (qrow_l + 8) * M_PITCH;
        #pragma unroll
        for (int nt = 0; nt < 8; nt++) {
            const int cb = 8 * nt + 2 * t;
            uint32_t m0 = *(const uint16_t*)(mrow0 + cb);
            uint32_t m1 = *(const uint16_t*)(mrow1 + cb);
            float e0 = (m0 & 0xffu)  ? 0.0f : __expf(c[nt][0] * QK_SCALE);
            float e1 = (m0 >> 8)     ? 0.0f : __expf(c[nt][1] * QK_SCALE);
            float e2 = (m1 & 0xffu)  ? 0.0f : __expf(c[nt][2] * QK_SCALE);
            float e3 = (m1 >> 8)     ? 0.0f : __expf(c[nt][3] * QK_SCALE);
            c[nt][0] = e0; c[nt][1] = e1; c[nt][2] = e2; c[nt][3] = e3;
            lsum0 += e0 + e1;
            lsum1 += e2 + e3;
            if (has_attn) {
                __stcs((float2*)(arow0 + cb), make_float2(e0, e1));
                __stcs((float2*)(arow1 + cb), make_float2(e2, e3));
            }
        }

        // ---- PV: O += E @ V. Convert C-frag(ks) -> A-frag via shuffles. ----
        #pragma unroll
        for (int ks = 0; ks < 8; ks++) {
            float v00 = __shfl_sync(0xffffffffu, c[ks][0], srcA);
            float v01 = __shfl_sync(0xffffffffu, c[ks][1], srcA);
            float v20 = __shfl_sync(0xffffffffu, c[ks][2], srcA);
            float v21 = __shfl_sync(0xffffffffu, c[ks][3], srcA);
            float w00 = __shfl_sync(0xffffffffu, c[ks][0], srcB);
            float w01 = __shfl_sync(0xffffffffu, c[ks][1], srcB);
            float w20 = __shfl_sync(0xffffffffu, c[ks][2], srcB);
            float w21 = __shfl_sync(0xffffffffu, c[ks][3], srcB);
            const uint32_t a0 = f2tf32(sel ? v01 : v00);
            const uint32_t a1 = f2tf32(sel ? v21 : v20);
            const uint32_t a2 = f2tf32(sel ? w01 : w00);
            const uint32_t a3 = f2tf32(sel ? w21 : w20);
            const int vr0 = 8 * ks + t;       // V rows for b0 / b1
            const int vr4 = vr0 + 4;
            #pragma unroll
            for (int nt = 0; nt < 16; nt++) {
                const int cc = (8 * nt + g) ^ (t << 3);
                const uint32_t b0 = Vs[vr0 * 128 + cc];
                const uint32_t b1 = Vs[vr4 * 128 + cc];
                mma_tf32(o[nt][0], o[nt][1], o[nt][2], o[nt][3], a0, a1, a2, a3, b0, b1);
            }
        }
    }

    // ---- reduce rowsums across the quad (lanes sharing a row) ----
    lsum0 += __shfl_xor_sync(0xffffffffu, lsum0, 1);
    lsum0 += __shfl_xor_sync(0xffffffffu, lsum0, 2);
    lsum1 += __shfl_xor_sync(0xffffffffu, lsum1, 1);
    lsum1 += __shfl_xor_sync(0xffffffffu, lsum1, 2);
    const float inv0 = 1.0f / lsum0;
    const float inv1 = 1.0f / lsum1;
    if (t == 0) {
        g_inv[qrow_g]     = inv0;
        g_inv[qrow_g + 8] = inv1;
    }

    // ---- epilogue: out = O / rowsum ----
    float* orow0 = outg + qrow_g * DD;
    float* orow1 = orow0 + 8 * (size_t)DD;
    #pragma unroll
    for (int nt = 0; nt < 16; nt++) {
        const int cb = 8 * nt + 2 * t;
        *(float2*)(orow0 + cb) = make_float2(o[nt][0] * inv0, o[nt][1] * inv0);
        *(float2*)(orow1 + cb) = make_float2(o[nt][2] * inv1, o[nt][3] * inv1);
    }
}

// ============================================================================
// Kernel B: attn[i] *= 1/rowsum. 8 independent float4 per thread (MLP=8).
// grid 8192 x 256 covers 16,777,216 float4 exactly.
// ============================================================================
__global__ void __launch_bounds__(256)
norm_kernel(float* __restrict__ attn) {
    const size_t i0 = (size_t)blockIdx.x * 256 + threadIdx.x;
    #pragma unroll
    for (int j = 0; j < 8; j++) {
        size_t i = i0 + (size_t)j * 2097152;
        float inv = g_inv[i >> 9];                     // 512 float4 per row
        float4 v = __ldcs((const float4*)attn + i);
        v.x *= inv; v.y *= inv; v.z *= inv; v.w *= inv;
        __stcs((float4*)attn + i, v);
    }
}

// ============================================================================
// Launch
// ============================================================================
extern "C" void kernel_launch(void* const* d_in, const int* in_sizes, int n_in,
                              void* d_out, int out_size) {
    const float* Q = (const float*)d_in[0];
    const float* K = (const float*)d_in[1];
    const float* V = (const float*)d_in[2];
    const void*  M = d_in[3];

    float* out = (float*)d_out;
    const long long out_elems  = (long long)BB * SQ * DD;              // 4,194,304
    const long long attn_elems = (long long)BB * SQ * SQ;              // 67,108,864
    int has_attn = ((long long)out_size >= out_elems + attn_elems) ? 1 : 0;
    float* attn = has_attn ? (out + out_elems) : out;   // dummy ptr if unused

    cudaFuncSetAttribute(attn_kernel,
                         cudaFuncAttributeMaxDynamicSharedMemorySize, SMEM_TOTAL);

    attn_kernel<<<dim3(SQ / 128, BB), 256, SMEM_TOTAL>>>(Q, K, V, M, out, attn, has_attn);
    if (has_attn)
        norm_kernel<<<8192, 256>>>(attn);
}